// round 12
// baseline (speedup 1.0000x reference)
#include <cuda_runtime.h>
#include <cuda_bf16.h>

// Fused quanvolution + linear + log_softmax, packed-f32x2 edition.
// One block = one sample. Threads 0..195 each own one 2x2 patch.
// Matvec t = U s computed as 8 row-pairs with fma.rn.f32x2 (FFMA2):
//   acc = {t[2rp], t[2rp+1]}, multiplier sv[f] broadcast into both halves.
// U stored in shared as packed row-pair float4s -> one broadcast LDS.128
// feeds two FFMA2s (4 U values).

#define NTHR 256

typedef unsigned long long ull;

__device__ __forceinline__ ull pk2(float lo, float hi) {
    ull r; asm("mov.b64 %0, {%1, %2};" : "=l"(r) : "f"(lo), "f"(hi)); return r;
}
__device__ __forceinline__ void unpk2(ull v, float& lo, float& hi) {
    asm("mov.b64 {%0, %1}, %2;" : "=f"(lo), "=f"(hi) : "l"(v));
}
__device__ __forceinline__ ull mul2(ull a, ull b) {
    ull r; asm("mul.rn.f32x2 %0, %1, %2;" : "=l"(r) : "l"(a), "l"(b)); return r;
}
__device__ __forceinline__ ull add2(ull a, ull b) {
    ull r; asm("add.rn.f32x2 %0, %1, %2;" : "=l"(r) : "l"(a), "l"(b)); return r;
}
__device__ __forceinline__ ull fma2(ull a, ull b, ull c) {
    ull r; asm("fma.rn.f32x2 %0, %1, %2, %3;" : "=l"(r) : "l"(a), "l"(b), "l"(c)); return r;
}

__global__ __launch_bounds__(NTHR, 3) void quanv_fused_kernel(
    const float* __restrict__ x,   // (B, 784)
    const float* __restrict__ U,   // (16, 16) row-major
    const float* __restrict__ W,   // (10, 784) row-major
    const float* __restrict__ bias,// (10)
    float* __restrict__ out)       // (B, 10)
{
    // Upk[rp][fp] = { {U[2rp][2fp],U[2rp+1][2fp]}, {U[2rp][2fp+1],U[2rp+1][2fp+1]} }
    __shared__ ulonglong2 Upk[8][8];
    __shared__ float feat[784];
    __shared__ float red[8 * 10];
    __shared__ float lg[10];

    const int tid = threadIdx.x;
    const int sample = blockIdx.x;
    const float* xs = x + (size_t)sample * 784;

    if (tid < 64) {
        const int rp = tid >> 3, fp = tid & 7;
        float a = U[(2 * rp)     * 16 + 2 * fp];
        float b = U[(2 * rp + 1) * 16 + 2 * fp];
        float c = U[(2 * rp)     * 16 + 2 * fp + 1];
        float d = U[(2 * rp + 1) * 16 + 2 * fp + 1];
        Upk[rp][fp] = make_ulonglong2(pk2(a, b), pk2(c, d));
    }
    __syncthreads();

    if (tid < 196) {
        const int r = tid / 14;
        const int c = tid - r * 14;
        const float2* row0 = (const float2*)(xs + (2 * r) * 28);
        const float2* row1 = (const float2*)(xs + (2 * r + 1) * 28);
        float2 top = row0[c];
        float2 bot = row1[c];

        float s0, c0, s1, c1, s2, c2, s3, c3;
        __sincosf(0.5f * top.x, &s0, &c0);
        __sincosf(0.5f * top.y, &s1, &c1);
        __sincosf(0.5f * bot.x, &s2, &c2);
        __sincosf(0.5f * bot.y, &s3, &c3);

        // Broadcast packed state: svb[f] = {sv[f], sv[f]}
        ull cb0 = pk2(c0, c0), sb0 = pk2(s0, s0);
        ull cb1 = pk2(c1, c1), sb1 = pk2(s1, s1);
        ull cb2 = pk2(c2, c2), sb2 = pk2(s2, s2);
        ull cb3 = pk2(c3, c3), sb3 = pk2(s3, s3);
        ull v01b[4] = { mul2(cb0, cb1), mul2(cb0, sb1), mul2(sb0, cb1), mul2(sb0, sb1) };
        ull v23b[4] = { mul2(cb2, cb3), mul2(cb2, sb3), mul2(sb2, cb3), mul2(sb2, sb3) };
        ull svb[16];
        #pragma unroll
        for (int m = 0; m < 4; m++)
            #pragma unroll
            for (int n = 0; n < 4; n++)
                svb[m * 4 + n] = mul2(v01b[m], v23b[n]);

        // Row-pair matvec: P[rp] = {p[2rp], p[2rp+1]}
        ull P[8];
        #pragma unroll
        for (int rp = 0; rp < 8; rp++) {
            ulonglong2 u0 = Upk[rp][0];
            ull acc = mul2(u0.x, svb[0]);
            acc = fma2(u0.y, svb[1], acc);
            #pragma unroll
            for (int fp = 1; fp < 8; fp++) {
                ulonglong2 u = Upk[rp][fp];
                acc = fma2(u.x, svb[2 * fp],     acc);
                acc = fma2(u.y, svb[2 * fp + 1], acc);
            }
            P[rp] = mul2(acc, acc);
        }

        // Walsh butterfly.
        // m3 = sum(p even) - sum(p odd) from packed total.
        ull T = add2(add2(add2(P[0], P[1]), add2(P[2], P[3])),
                     add2(add2(P[4], P[5]), add2(P[6], P[7])));
        float tl, th;  unpk2(T, tl, th);
        float m3 = tl - th;

        float g8[8];
        #pragma unroll
        for (int i = 0; i < 8; i++) {
            float plo, phi; unpk2(P[i], plo, phi);
            g8[i] = plo + phi;
        }
        float m2 = (g8[0] - g8[1]) + (g8[2] - g8[3]) + (g8[4] - g8[5]) + (g8[6] - g8[7]);
        float g4_0 = g8[0] + g8[1], g4_1 = g8[2] + g8[3];
        float g4_2 = g8[4] + g8[5], g4_3 = g8[6] + g8[7];
        float m1 = (g4_0 - g4_1) + (g4_2 - g4_3);
        float m0 = (g4_0 + g4_1) - (g4_2 + g4_3);

        ((float4*)feat)[tid] = make_float4(m0, m1, m2, m3);
    }
    __syncthreads();

    // Linear: logits[c] = sum_j feat[j] * W[c][j] + b[c]
    float partial[10];
    #pragma unroll
    for (int c = 0; c < 10; c++) partial[c] = 0.f;

    if (tid < 196) {
        float4 f4 = ((const float4*)feat)[tid];
        #pragma unroll
        for (int c = 0; c < 10; c++) {
            float4 w4 = ((const float4*)(W + c * 784))[tid];
            float acc = f4.x * w4.x;
            acc = fmaf(f4.y, w4.y, acc);
            acc = fmaf(f4.z, w4.z, acc);
            acc = fmaf(f4.w, w4.w, acc);
            partial[c] = acc;
        }
    }

    #pragma unroll
    for (int c = 0; c < 10; c++) {
        #pragma unroll
        for (int o = 16; o > 0; o >>= 1)
            partial[c] += __shfl_xor_sync(0xffffffffu, partial[c], o);
    }
    const int warp = tid >> 5;
    const int lane = tid & 31;
    if (lane == 0) {
        #pragma unroll
        for (int c = 0; c < 10; c++) red[warp * 10 + c] = partial[c];
    }
    __syncthreads();

    if (tid < 10) {
        float v = bias[tid];
        #pragma unroll
        for (int w = 0; w < 8; w++) v += red[w * 10 + tid];
        lg[tid] = v;
    }
    __syncthreads();

    if (tid < 10) {
        float mx = lg[0];
        #pragma unroll
        for (int i = 1; i < 10; i++) mx = fmaxf(mx, lg[i]);
        float s = 0.f;
        #pragma unroll
        for (int i = 0; i < 10; i++) s += __expf(lg[i] - mx);
        out[(size_t)sample * 10 + tid] = lg[tid] - mx - __logf(s);
    }
}

extern "C" void kernel_launch(void* const* d_in, const int* in_sizes, int n_in,
                              void* d_out, int out_size) {
    const float* x  = (const float*)d_in[0];
    const float* U  = (const float*)d_in[1];
    const float* W  = (const float*)d_in[2];
    const float* b  = (const float*)d_in[3];
    float* out = (float*)d_out;
    int B = in_sizes[0] / 784;
    quanv_fused_kernel<<<B, NTHR>>>(x, U, W, b, out);
}

// round 13
// speedup vs baseline: 1.5252x; 1.5252x over previous
#include <cuda_runtime.h>
#include <cuda_bf16.h>

// Fused quanvolution + linear + log_softmax.
// One block = one sample; threads 0..195 own one 2x2 patch each.
// Matvec t = U s with K-paired fma.rn.f32x2:
//   acc2_e = sum_fp {U[e][2fp],U[e][2fp+1]} * {sv[2fp],sv[2fp+1]}  (packed)
//   t_e = lo(acc2_e) + hi(acc2_e)
// U element pairs are ADJACENT in row-major U -> each is one aligned
// LDCU.64 from __constant__ (uniform port; no L1/shared-pipe traffic).

#define NTHR 256

typedef unsigned long long ull;

__constant__ ull Uc64[128];   // U (16x16 fp32) viewed as 128 adjacent pairs

__device__ __forceinline__ ull pk2(float lo, float hi) {
    ull r; asm("mov.b64 %0, {%1, %2};" : "=l"(r) : "f"(lo), "f"(hi)); return r;
}
__device__ __forceinline__ void unpk2(ull v, float& lo, float& hi) {
    asm("mov.b64 {%0, %1}, %2;" : "=f"(lo), "=f"(hi) : "l"(v));
}
__device__ __forceinline__ ull mul2(ull a, ull b) {
    ull r; asm("mul.rn.f32x2 %0, %1, %2;" : "=l"(r) : "l"(a), "l"(b)); return r;
}
__device__ __forceinline__ ull fma2(ull a, ull b, ull c) {
    ull r; asm("fma.rn.f32x2 %0, %1, %2, %3;" : "=l"(r) : "l"(a), "l"(b), "l"(c)); return r;
}

__global__ __launch_bounds__(NTHR) void quanv_fused_kernel(
    const float* __restrict__ x,   // (B, 784)
    const float* __restrict__ W,   // (10, 784) row-major
    const float* __restrict__ bias,// (10)
    float* __restrict__ out)       // (B, 10)
{
    __shared__ float feat[784];
    __shared__ float red[8 * 10];
    __shared__ float lg[10];

    const int tid = threadIdx.x;
    const int sample = blockIdx.x;
    const float* xs = x + (size_t)sample * 784;

    if (tid < 196) {
        const int r = tid / 14;
        const int c = tid - r * 14;
        const float2* row0 = (const float2*)(xs + (2 * r) * 28);
        const float2* row1 = (const float2*)(xs + (2 * r + 1) * 28);
        float2 top = row0[c];
        float2 bot = row1[c];

        float s0, c0, s1, c1, s2, c2, s3, c3;
        __sincosf(0.5f * top.x, &s0, &c0);
        __sincosf(0.5f * top.y, &s1, &c1);
        __sincosf(0.5f * bot.x, &s2, &c2);
        __sincosf(0.5f * bot.y, &s3, &c3);

        // product state, index = i*8 + j*4 + k*2 + l (wire 0 = MSB)
        float v01[4] = { c0 * c1, c0 * s1, s0 * c1, s0 * s1 };
        float v23[4] = { c2 * c3, c2 * s3, s2 * c3, s2 * s3 };
        float sv[16];
        #pragma unroll
        for (int m = 0; m < 4; m++)
            #pragma unroll
            for (int n = 0; n < 4; n++)
                sv[m * 4 + n] = v01[m] * v23[n];

        // Pack adjacent state pairs: svp[fp] = {sv[2fp], sv[2fp+1]}
        ull svp[8];
        #pragma unroll
        for (int fp = 0; fp < 8; fp++)
            svp[fp] = pk2(sv[2 * fp], sv[2 * fp + 1]);

        // t_e = sum_f U[e][f]*sv[f], packed over K-pairs; U pairs via LDCU.64
        float p[16];
        #pragma unroll
        for (int e = 0; e < 16; e++) {
            ull acc = mul2(Uc64[e * 8 + 0], svp[0]);
            #pragma unroll
            for (int fp = 1; fp < 8; fp++)
                acc = fma2(Uc64[e * 8 + fp], svp[fp], acc);
            float lo, hi; unpk2(acc, lo, hi);
            float t = lo + hi;
            p[e] = t * t;
        }

        // Walsh butterfly: meas_q = sum_e (1 - 2*bit_{3-q}(e)) * p[e]
        float m3 = 0.f, m2 = 0.f, m1 = 0.f, m0;
        float g8[8];
        #pragma unroll
        for (int i = 0; i < 8; i++) {
            g8[i] = p[2 * i] + p[2 * i + 1];
            m3   += p[2 * i] - p[2 * i + 1];
        }
        float g4[4];
        #pragma unroll
        for (int i = 0; i < 4; i++) {
            g4[i] = g8[2 * i] + g8[2 * i + 1];
            m2   += g8[2 * i] - g8[2 * i + 1];
        }
        float g2[2];
        #pragma unroll
        for (int i = 0; i < 2; i++) {
            g2[i] = g4[2 * i] + g4[2 * i + 1];
            m1   += g4[2 * i] - g4[2 * i + 1];
        }
        m0 = g2[0] - g2[1];

        ((float4*)feat)[tid] = make_float4(m0, m1, m2, m3);
    }
    __syncthreads();

    // Linear: logits[c] = sum_j feat[j] * W[c][j] + b[c]
    float partial[10];
    #pragma unroll
    for (int c = 0; c < 10; c++) partial[c] = 0.f;

    if (tid < 196) {
        float4 f4 = ((const float4*)feat)[tid];
        #pragma unroll
        for (int c = 0; c < 10; c++) {
            float4 w4 = ((const float4*)(W + c * 784))[tid];
            float acc = f4.x * w4.x;
            acc = fmaf(f4.y, w4.y, acc);
            acc = fmaf(f4.z, w4.z, acc);
            acc = fmaf(f4.w, w4.w, acc);
            partial[c] = acc;
        }
    }

    #pragma unroll
    for (int c = 0; c < 10; c++) {
        #pragma unroll
        for (int o = 16; o > 0; o >>= 1)
            partial[c] += __shfl_xor_sync(0xffffffffu, partial[c], o);
    }
    const int warp = tid >> 5;
    const int lane = tid & 31;
    if (lane == 0) {
        #pragma unroll
        for (int c = 0; c < 10; c++) red[warp * 10 + c] = partial[c];
    }
    __syncthreads();

    if (tid < 10) {
        float v = bias[tid];
        #pragma unroll
        for (int w = 0; w < 8; w++) v += red[w * 10 + tid];
        lg[tid] = v;
    }
    __syncthreads();

    if (tid < 10) {
        float mx = lg[0];
        #pragma unroll
        for (int i = 1; i < 10; i++) mx = fmaxf(mx, lg[i]);
        float s = 0.f;
        #pragma unroll
        for (int i = 0; i < 10; i++) s += __expf(lg[i] - mx);
        out[(size_t)sample * 10 + tid] = lg[tid] - mx - __logf(s);
    }
}

extern "C" void kernel_launch(void* const* d_in, const int* in_sizes, int n_in,
                              void* d_out, int out_size) {
    const float* x  = (const float*)d_in[0];
    const float* U  = (const float*)d_in[1];
    const float* W  = (const float*)d_in[2];
    const float* b  = (const float*)d_in[3];
    float* out = (float*)d_out;
    int B = in_sizes[0] / 784;
    cudaMemcpyToSymbolAsync(Uc64, U, 256 * sizeof(float), 0,
                            cudaMemcpyDeviceToDevice);
    quanv_fused_kernel<<<B, NTHR>>>(x, W, b, out);
}